// round 3
// baseline (speedup 1.0000x reference)
#include <cuda_runtime.h>

#define BATCH 16384
#define BAG   30
#define H1    256
#define H2    32

// Inputs (metadata order):
// 0: white_indices int32 [B*BAG]
// 1: white_offsets (ignored)
// 2: black_indices int32 [B*BAG]
// 3: black_offsets (ignored)
// 4: ft_white f32 [41025, 256]
// 5: ft_black f32 [41025, 256]
// 6: fc1_w f32 [32, 512]
// 7: fc1_b f32 [32]
// 8: fc2_w f32 [32, 32]
// 9: fc2_b f32 [32]
// 10: fc3_w f32 [1, 32]
// 11: fc3_b f32 [1]
// out: f32 [B]

__global__ __launch_bounds__(256, 8)
void nnue_kernel(const int* __restrict__ wi,
                 const int* __restrict__ bi,
                 const float* __restrict__ ftw,
                 const float* __restrict__ ftb,
                 const float* __restrict__ fc1w,
                 const float* __restrict__ fc1b,
                 const float* __restrict__ fc2w,
                 const float* __restrict__ fc2b,
                 const float* __restrict__ fc3w,
                 const float* __restrict__ fc3b,
                 float* __restrict__ out)
{
    __shared__ int   sidx[2][BAG];
    __shared__ float x[2 * H1];     // concat(white, black) after relu
    __shared__ float h1[H2];

    const int p    = blockIdx.x;
    const int tid  = threadIdx.x;
    const int lane = tid & 31;
    const int warp = tid >> 5;

    // Load the 2x30 indices for this position into smem.
    if (tid < BAG) {
        sidx[0][tid] = wi[p * BAG + tid];
    } else if (tid >= 32 && tid < 32 + BAG) {
        sidx[1][tid - 32] = bi[p * BAG + (tid - 32)];
    }
    __syncthreads();

    // EmbeddingBag sum: thread tid owns column tid of each table.
    // 60 independent LDGs per thread -> high MLP, coalesced 128B/warp.
    float accw = 0.0f, accb = 0.0f;
#pragma unroll 6
    for (int j = 0; j < BAG; j++) {
        const int iw = sidx[0][j];
        const int ib = sidx[1][j];
        accw += __ldg(&ftw[(size_t)iw * H1 + tid]);
        accb += __ldg(&ftb[(size_t)ib * H1 + tid]);
    }
    x[tid]      = fmaxf(accw, 0.0f);
    x[tid + H1] = fmaxf(accb, 0.0f);
    __syncthreads();

    // FC1: 512 -> 32, relu. 8 warps, 4 outputs each; 16 MACs/lane/output
    // then butterfly reduce.
#pragma unroll
    for (int q = 0; q < 4; q++) {
        const int o = warp * 4 + q;
        const float* wrow = fc1w + (size_t)o * 512;
        float part = 0.0f;
#pragma unroll
        for (int i = 0; i < 16; i++) {
            part += x[lane + 32 * i] * __ldg(&wrow[lane + 32 * i]);
        }
#pragma unroll
        for (int off = 16; off > 0; off >>= 1)
            part += __shfl_xor_sync(0xffffffffu, part, off);
        if (lane == 0)
            h1[o] = fmaxf(part + __ldg(&fc1b[o]), 0.0f);
    }
    __syncthreads();

    // FC2 (32->32, relu) + FC3 (32->1) on warp 0.
    if (warp == 0) {
        float s = __ldg(&fc2b[lane]);
        const float* w2 = fc2w + (size_t)lane * 32;
#pragma unroll
        for (int j = 0; j < 32; j++)
            s += h1[j] * __ldg(&w2[j]);
        float v = fmaxf(s, 0.0f) * __ldg(&fc3w[lane]);
#pragma unroll
        for (int off = 16; off > 0; off >>= 1)
            v += __shfl_xor_sync(0xffffffffu, v, off);
        if (lane == 0)
            out[p] = v + __ldg(&fc3b[0]);
    }
}

extern "C" void kernel_launch(void* const* d_in, const int* in_sizes, int n_in,
                              void* d_out, int out_size)
{
    const int*   wi   = (const int*)d_in[0];
    const int*   bi   = (const int*)d_in[2];
    const float* ftw  = (const float*)d_in[4];
    const float* ftb  = (const float*)d_in[5];
    const float* fc1w = (const float*)d_in[6];
    const float* fc1b = (const float*)d_in[7];
    const float* fc2w = (const float*)d_in[8];
    const float* fc2b = (const float*)d_in[9];
    const float* fc3w = (const float*)d_in[10];
    const float* fc3b = (const float*)d_in[11];
    float* out = (float*)d_out;

    nnue_kernel<<<BATCH, 256>>>(wi, bi, ftw, ftb, fc1w, fc1b,
                                fc2w, fc2b, fc3w, fc3b, out);
}

// round 4
// speedup vs baseline: 1.9905x; 1.9905x over previous
#include <cuda_runtime.h>

#define BATCH 16384
#define BAG   30
#define P     8          // positions per block
#define NT    256
#define GRID  (BATCH / P)

// Inputs (metadata order):
// 0: white_indices int32 [B*BAG]   2: black_indices int32 [B*BAG]
// 4: ft_white f32 [41025,256]      5: ft_black f32 [41025,256]
// 6: fc1_w f32 [32,512]  7: fc1_b  8: fc2_w f32 [32,32]  9: fc2_b
// 10: fc3_w f32 [1,32]  11: fc3_b     out: f32 [B]

__global__ __launch_bounds__(NT, 2)
void nnue_kernel(const int* __restrict__ wi,
                 const int* __restrict__ bi,
                 const float4* __restrict__ ftw,    // [NUM_EMB][64] float4
                 const float4* __restrict__ ftb,
                 const float4* __restrict__ fc1w,   // [32][128] float4
                 const float* __restrict__ fc1b,
                 const float4* __restrict__ fc2w,   // [32][8] float4
                 const float* __restrict__ fc2b,
                 const float* __restrict__ fc3w,
                 const float* __restrict__ fc3b,
                 float* __restrict__ out)
{
    __shared__ int    s_idx[P][2][BAG];
    __shared__ float4 s_x[P][128];     // concat(white,black) after relu, as float4
    __shared__ float  s_h1[P][32];

    const int tid  = threadIdx.x;
    const int lane = tid & 31;
    const int warp = tid >> 5;
    const int p0   = blockIdx.x * P;

    // ---- stage indices for the 8 positions ----
    for (int i = tid; i < P * 2 * BAG; i += NT) {
        const int pp  = i / (2 * BAG);
        const int r   = i % (2 * BAG);
        const int tbl = r / BAG;
        const int j   = r % BAG;
        s_idx[pp][tbl][j] = tbl ? bi[(p0 + pp) * BAG + j]
                                : wi[(p0 + pp) * BAG + j];
    }
    __syncthreads();

    // ---- EmbeddingBag gather (float4, both tables) ----
    // thread -> (c4 = float4 column 0..63, grp = 0..3); grp handles positions
    // {2g, 2g+1} for both tables. Whole warp shares grp -> uniform sidx reads.
    {
        const int c4  = tid & 63;
        const int grp = tid >> 6;
#pragma unroll
        for (int pp = 0; pp < 2; pp++) {
            const int pos = 2 * grp + pp;
            float4 aw = make_float4(0.f, 0.f, 0.f, 0.f);
            float4 ab = make_float4(0.f, 0.f, 0.f, 0.f);
#pragma unroll 6
            for (int j = 0; j < BAG; j++) {
                const int iw = s_idx[pos][0][j];
                const int ib = s_idx[pos][1][j];
                const float4 vw = __ldg(&ftw[(size_t)iw * 64 + c4]);
                const float4 vb = __ldg(&ftb[(size_t)ib * 64 + c4]);
                aw.x += vw.x; aw.y += vw.y; aw.z += vw.z; aw.w += vw.w;
                ab.x += vb.x; ab.y += vb.y; ab.z += vb.z; ab.w += vb.w;
            }
            aw.x = fmaxf(aw.x, 0.f); aw.y = fmaxf(aw.y, 0.f);
            aw.z = fmaxf(aw.z, 0.f); aw.w = fmaxf(aw.w, 0.f);
            ab.x = fmaxf(ab.x, 0.f); ab.y = fmaxf(ab.y, 0.f);
            ab.z = fmaxf(ab.z, 0.f); ab.w = fmaxf(ab.w, 0.f);
            s_x[pos][c4]      = aw;   // white -> x[0..255]
            s_x[pos][64 + c4] = ab;   // black -> x[256..511]
        }
    }

    // ---- FC1 weights -> registers (once per block, overlaps the barrier) ----
    // warp owns outputs 4*warp .. 4*warp+3; lane covers f4 indices lane+32k.
    float4 wreg[4][4];
    float  b1[4];
#pragma unroll
    for (int oo = 0; oo < 4; oo++) {
        const int o = 4 * warp + oo;
#pragma unroll
        for (int k = 0; k < 4; k++)
            wreg[oo][k] = __ldg(&fc1w[(size_t)o * 128 + lane + 32 * k]);
        b1[oo] = __ldg(&fc1b[o]);
    }
    __syncthreads();

    // ---- FC1: each warp computes its 4 outputs for all 8 positions ----
#pragma unroll
    for (int pos = 0; pos < P; pos++) {
        float4 xr[4];
#pragma unroll
        for (int k = 0; k < 4; k++)
            xr[k] = s_x[pos][lane + 32 * k];

        float part[4];
#pragma unroll
        for (int oo = 0; oo < 4; oo++) {
            float s = 0.f;
#pragma unroll
            for (int k = 0; k < 4; k++) {
                s += wreg[oo][k].x * xr[k].x;
                s += wreg[oo][k].y * xr[k].y;
                s += wreg[oo][k].z * xr[k].z;
                s += wreg[oo][k].w * xr[k].w;
            }
            part[oo] = s;
        }
#pragma unroll
        for (int off = 16; off > 0; off >>= 1) {
#pragma unroll
            for (int oo = 0; oo < 4; oo++)
                part[oo] += __shfl_xor_sync(0xffffffffu, part[oo], off);
        }
        if (lane == 0) {
#pragma unroll
            for (int oo = 0; oo < 4; oo++)
                s_h1[pos][4 * warp + oo] = fmaxf(part[oo] + b1[oo], 0.f);
        }
    }
    __syncthreads();

    // ---- FC2 (32->32, relu) + FC3 (32->1): warp w handles position w ----
    {
        const int pos = warp;
        const float* h = s_h1[pos];
        float s = __ldg(&fc2b[lane]);
        const float4* w2 = fc2w + (size_t)lane * 8;
#pragma unroll
        for (int k = 0; k < 8; k++) {
            const float4 w = __ldg(&w2[k]);
            s += w.x * h[4 * k + 0];
            s += w.y * h[4 * k + 1];
            s += w.z * h[4 * k + 2];
            s += w.w * h[4 * k + 3];
        }
        float v = fmaxf(s, 0.f) * __ldg(&fc3w[lane]);
#pragma unroll
        for (int off = 16; off > 0; off >>= 1)
            v += __shfl_xor_sync(0xffffffffu, v, off);
        if (lane == 0)
            out[p0 + pos] = v + __ldg(&fc3b[0]);
    }
}

extern "C" void kernel_launch(void* const* d_in, const int* in_sizes, int n_in,
                              void* d_out, int out_size)
{
    const int*    wiP   = (const int*)d_in[0];
    const int*    biP   = (const int*)d_in[2];
    const float4* ftw   = (const float4*)d_in[4];
    const float4* ftb   = (const float4*)d_in[5];
    const float4* fc1w  = (const float4*)d_in[6];
    const float*  fc1b  = (const float*)d_in[7];
    const float4* fc2w  = (const float4*)d_in[8];
    const float*  fc2b  = (const float*)d_in[9];
    const float*  fc3w  = (const float*)d_in[10];
    const float*  fc3b  = (const float*)d_in[11];
    float* out = (float*)d_out;

    nnue_kernel<<<GRID, NT>>>(wiP, biP, ftw, ftb, fc1w, fc1b,
                              fc2w, fc2b, fc3w, fc3b, out);
}